// round 3
// baseline (speedup 1.0000x reference)
#include <cuda_runtime.h>

#define SEQ 20
#define DK  64
#define BHB 4          // (b,h) problems per block
#define THREADS (BHB * SEQ)   // 80: one thread per (bh, q-row)

typedef unsigned long long ull;

// packed f32x2 FMA: d = a*b + c elementwise on (lo,hi) float pairs
__device__ __forceinline__ ull fma2(ull a, ull b, ull c) {
    ull d;
    asm("fma.rn.f32x2 %0, %1, %2, %3;" : "=l"(d) : "l"(a), "l"(b), "l"(c));
    return d;
}
__device__ __forceinline__ ull pack2(float lo, float hi) {
    ull r;
    asm("mov.b64 %0, {%1, %2};" : "=l"(r) : "f"(lo), "f"(hi));
    return r;
}
__device__ __forceinline__ float2 unpack2(ull v) {
    float2 r;
    asm("mov.b64 {%0, %1}, %2;" : "=f"(r.x), "=f"(r.y) : "l"(v));
    return r;
}

__global__ __launch_bounds__(THREADS)
void sdpa_rel_kernel(const float* __restrict__ Qg,
                     const float* __restrict__ Kg,
                     const float* __restrict__ Vg,
                     const float* __restrict__ Mg,
                     float* __restrict__ deAtt,
                     float* __restrict__ attnOut)
{
    __shared__ __align__(16) float sK[BHB][SEQ * DK];
    __shared__ __align__(16) float sV[BHB][SEQ * DK];

    const int tid = threadIdx.x;
    const long bh0 = (long)blockIdx.x * BHB;

    // ---- Stage K,V (coalesced float4) ----
    for (int i = tid; i < BHB * (SEQ * DK / 4); i += THREADS) {
        int b = i / (SEQ * DK / 4);
        int j = i % (SEQ * DK / 4);
        const long base4 = (bh0 + b) * (long)(SEQ * DK / 4);
        ((float4*)sK[b])[j] = ((const float4*)Kg)[base4 + j];
        ((float4*)sV[b])[j] = ((const float4*)Vg)[base4 + j];
    }
    __syncthreads();   // the only block-wide sync

    const int b = tid / SEQ;
    const int q = tid % SEQ;
    const long bh = bh0 + b;

    // ---- Phase A: S[q][*] = Q[q] . K^T, f32x2 (even-d, odd-d) partial pairs ----
    ull acc2[SEQ];
    #pragma unroll
    for (int k = 0; k < SEQ; k++) acc2[k] = 0ull;

    const ulonglong2* Qrow = (const ulonglong2*)(Qg + bh * (long)(SEQ * DK) + q * DK);
    #pragma unroll 4
    for (int d4 = 0; d4 < DK / 4; d4++) {
        ulonglong2 qp = Qrow[d4];          // (q0,q1),(q2,q3)
        #pragma unroll
        for (int k = 0; k < SEQ; k++) {
            ulonglong2 kp = *(const ulonglong2*)&sK[b][k * DK + d4 * 4];
            acc2[k] = fma2(qp.x, kp.x, acc2[k]);
            acc2[k] = fma2(qp.y, kp.y, acc2[k]);
        }
    }

    // ---- exp(scale*S)*mask, row-sum, normalize — all in registers ----
    const float4* Mrow = (const float4*)(Mg + bh * (long)(SEQ * SEQ) + q * SEQ);
    float s[SEQ];
    float sum = 0.f;
    #pragma unroll
    for (int k4 = 0; k4 < SEQ / 4; k4++) {
        float4 m = Mrow[k4];
        float2 p;
        p = unpack2(acc2[k4 * 4 + 0]); s[k4 * 4 + 0] = __expf((p.x + p.y) * 0.125f) * m.x;
        p = unpack2(acc2[k4 * 4 + 1]); s[k4 * 4 + 1] = __expf((p.x + p.y) * 0.125f) * m.y;
        p = unpack2(acc2[k4 * 4 + 2]); s[k4 * 4 + 2] = __expf((p.x + p.y) * 0.125f) * m.z;
        p = unpack2(acc2[k4 * 4 + 3]); s[k4 * 4 + 3] = __expf((p.x + p.y) * 0.125f) * m.w;
        sum += s[k4 * 4 + 0] + s[k4 * 4 + 1] + s[k4 * 4 + 2] + s[k4 * 4 + 3];
    }
    const float inv = 1.0f / (sum + 1e-8f);

    // write attn row; build W = attn - |q-k| as (w,w) pairs for f32x2
    float4* Arow = (float4*)(attnOut + bh * (long)(SEQ * SEQ) + q * SEQ);
    ull w2[SEQ];
    #pragma unroll
    for (int k4 = 0; k4 < SEQ / 4; k4++) {
        float a0 = s[k4 * 4 + 0] * inv;
        float a1 = s[k4 * 4 + 1] * inv;
        float a2 = s[k4 * 4 + 2] * inv;
        float a3 = s[k4 * 4 + 3] * inv;
        Arow[k4] = make_float4(a0, a1, a2, a3);
        float w0 = a0 - fabsf((float)(q - (k4 * 4 + 0)));
        float w1 = a1 - fabsf((float)(q - (k4 * 4 + 1)));
        float w2v = a2 - fabsf((float)(q - (k4 * 4 + 2)));
        float w3 = a3 - fabsf((float)(q - (k4 * 4 + 3)));
        w2[k4 * 4 + 0] = pack2(w0, w0);
        w2[k4 * 4 + 1] = pack2(w1, w1);
        w2[k4 * 4 + 2] = pack2(w2v, w2v);
        w2[k4 * 4 + 3] = pack2(w3, w3);
    }

    // ---- Phase C: deAtt[q] = W[q] @ V, f32x2 over d-pairs ----
    float4* Orow = (float4*)(deAtt + bh * (long)(SEQ * DK) + q * DK);
    #pragma unroll 4
    for (int d4 = 0; d4 < DK / 4; d4++) {
        ull a01 = 0ull, a23 = 0ull;
        #pragma unroll
        for (int k = 0; k < SEQ; k++) {
            ulonglong2 vp = *(const ulonglong2*)&sV[b][k * DK + d4 * 4];
            a01 = fma2(w2[k], vp.x, a01);
            a23 = fma2(w2[k], vp.y, a23);
        }
        float2 lo = unpack2(a01);
        float2 hi = unpack2(a23);
        Orow[d4] = make_float4(lo.x, lo.y, hi.x, hi.y);
    }
}

extern "C" void kernel_launch(void* const* d_in, const int* in_sizes, int n_in,
                              void* d_out, int out_size)
{
    const float* Q = (const float*)d_in[0];
    const float* K = (const float*)d_in[1];
    const float* V = (const float*)d_in[2];
    const float* M = (const float*)d_in[3];

    const int bh = in_sizes[0] / (SEQ * DK);   // 8192

    float* deAtt   = (float*)d_out;                      // [bh, SEQ, DK]
    float* attnOut = (float*)d_out + (long)in_sizes[0];  // [bh, SEQ, SEQ]

    const int grid = bh / BHB;                           // 2048
    sdpa_rel_kernel<<<grid, THREADS>>>(Q, K, V, M, deAtt, attnOut);
}

// round 4
// speedup vs baseline: 1.1611x; 1.1611x over previous
#include <cuda_runtime.h>

#define SEQ 20
#define DK  64
#define BHB 2        // (b,h) problems per block
#define THREADS 256

#define QS 68        // Q,K smem row stride (16B-aligned rows)
#define VS 68        // V smem row stride
#define WS 21        // scores/W smem row stride

typedef unsigned long long ull;

__device__ __forceinline__ ull fma2(ull a, ull b, ull c) {
    ull d;
    asm("fma.rn.f32x2 %0, %1, %2, %3;" : "=l"(d) : "l"(a), "l"(b), "l"(c));
    return d;
}
__device__ __forceinline__ float2 unpack2(ull v) {
    float2 r;
    asm("mov.b64 {%0, %1}, %2;" : "=f"(r.x), "=f"(r.y) : "l"(v));
    return r;
}

__global__ __launch_bounds__(THREADS)
void sdpa_rel_kernel(const float* __restrict__ Qg,
                     const float* __restrict__ Kg,
                     const float* __restrict__ Vg,
                     const float* __restrict__ Mg,
                     float* __restrict__ deAtt,
                     float* __restrict__ attnOut)
{
    __shared__ __align__(16) float sQ[BHB][SEQ * QS];
    __shared__ __align__(16) float sK[BHB][SEQ * QS];
    __shared__ __align__(16) float sV[BHB][SEQ * VS];
    __shared__ float sS[BHB][SEQ * WS];
    __shared__ float sInv[BHB][SEQ];

    const int tid = threadIdx.x;
    const long bh0 = (long)blockIdx.x * BHB;

    // ---- Stage Q,K,V tiles into smem (coalesced float4) ----
    for (int i = tid; i < BHB * (SEQ * DK / 4); i += THREADS) {
        int b   = i / (SEQ * DK / 4);
        int j   = i % (SEQ * DK / 4);
        int row = j / (DK / 4);
        int c4  = j % (DK / 4);
        const long base = (bh0 + b) * (long)(SEQ * DK);
        float4 q = ((const float4*)(Qg + base))[j];
        float4 k = ((const float4*)(Kg + base))[j];
        float4 v = ((const float4*)(Vg + base))[j];
        *((float4*)(&sQ[b][row * QS + 4 * c4])) = q;
        *((float4*)(&sK[b][row * QS + 4 * c4])) = k;
        *((float4*)(&sV[b][row * VS + 4 * c4])) = v;
    }
    __syncthreads();

    // ---- Phase A: S = Q K^T, 2q x 2k tiles, f32x2 over d-pairs (200 active) ----
    if (tid < BHB * 100) {
        int b  = tid / 100;
        int t  = tid % 100;
        int q0 = (t / 10) * 2;
        int k0 = (t % 10) * 2;
        ull a00 = 0ull, a01 = 0ull, a10 = 0ull, a11 = 0ull;
        const float* qr0 = &sQ[b][q0 * QS];
        const float* qr1 = &sQ[b][(q0 + 1) * QS];
        const float* kr0 = &sK[b][k0 * QS];
        const float* kr1 = &sK[b][(k0 + 1) * QS];
        #pragma unroll 8
        for (int d2 = 0; d2 < DK / 2; d2++) {
            ull qp0 = *(const ull*)(qr0 + 2 * d2);
            ull qp1 = *(const ull*)(qr1 + 2 * d2);
            ull kp0 = *(const ull*)(kr0 + 2 * d2);
            ull kp1 = *(const ull*)(kr1 + 2 * d2);
            a00 = fma2(qp0, kp0, a00);
            a01 = fma2(qp0, kp1, a01);
            a10 = fma2(qp1, kp0, a10);
            a11 = fma2(qp1, kp1, a11);
        }
        float2 p;
        p = unpack2(a00); sS[b][q0 * WS + k0]           = p.x + p.y;
        p = unpack2(a01); sS[b][q0 * WS + k0 + 1]       = p.x + p.y;
        p = unpack2(a10); sS[b][(q0 + 1) * WS + k0]     = p.x + p.y;
        p = unpack2(a11); sS[b][(q0 + 1) * WS + k0 + 1] = p.x + p.y;
    }
    __syncthreads();

    // ---- exp(scale * S) * mask (mask read coalesced from global) ----
    for (int e = tid; e < BHB * SEQ * SEQ; e += THREADS) {
        int b = e / (SEQ * SEQ);
        int j = e % (SEQ * SEQ);
        int q = j / SEQ, k = j % SEQ;
        float raw = sS[b][q * WS + k];
        sS[b][q * WS + k] = __expf(raw * 0.125f) * Mg[(bh0 + b) * (long)(SEQ * SEQ) + j];
    }
    __syncthreads();

    // ---- row sums -> reciprocal ----
    if (tid < BHB * SEQ) {
        int b = tid / SEQ, q = tid % SEQ;
        float s = 0.f;
        #pragma unroll
        for (int k = 0; k < SEQ; k++) s += sS[b][q * WS + k];
        sInv[b][q] = 1.0f / (s + 1e-8f);
    }
    __syncthreads();

    // ---- normalize -> write attn; form W = attn - |q-k| in place ----
    for (int e = tid; e < BHB * SEQ * SEQ; e += THREADS) {
        int b = e / (SEQ * SEQ);
        int j = e % (SEQ * SEQ);
        int q = j / SEQ, k = j % SEQ;
        float a = sS[b][q * WS + k] * sInv[b][q];
        attnOut[(bh0 + b) * (long)(SEQ * SEQ) + j] = a;
        sS[b][q * WS + k] = a - fabsf((float)(q - k));
    }
    __syncthreads();

    // ---- Phase C: deAtt = W @ V, 4q x 4d register tiles (160 active) ----
    if (tid < BHB * 80) {
        int b    = tid / 80;
        int tile = tid % 80;
        int q0 = (tile / 16) * 4;
        int d0 = (tile % 16) * 4;
        float4 acc[4];
        #pragma unroll
        for (int i = 0; i < 4; i++) acc[i] = make_float4(0.f, 0.f, 0.f, 0.f);
        #pragma unroll
        for (int k = 0; k < SEQ; k++) {
            float4 v = *((const float4*)(&sV[b][k * VS + d0]));
            #pragma unroll
            for (int i = 0; i < 4; i++) {
                float w = sS[b][(q0 + i) * WS + k];
                acc[i].x = fmaf(w, v.x, acc[i].x);
                acc[i].y = fmaf(w, v.y, acc[i].y);
                acc[i].z = fmaf(w, v.z, acc[i].z);
                acc[i].w = fmaf(w, v.w, acc[i].w);
            }
        }
        const long base = (bh0 + b) * (long)(SEQ * DK);
        #pragma unroll
        for (int i = 0; i < 4; i++)
            *((float4*)(deAtt + base + (q0 + i) * DK + d0)) = acc[i];
    }
}

extern "C" void kernel_launch(void* const* d_in, const int* in_sizes, int n_in,
                              void* d_out, int out_size)
{
    const float* Q = (const float*)d_in[0];
    const float* K = (const float*)d_in[1];
    const float* V = (const float*)d_in[2];
    const float* M = (const float*)d_in[3];

    const int bh = in_sizes[0] / (SEQ * DK);   // 8192

    float* deAtt   = (float*)d_out;                      // [bh, SEQ, DK]
    float* attnOut = (float*)d_out + (long)in_sizes[0];  // [bh, SEQ, SEQ]

    const int grid = bh / BHB;                           // 4096
    sdpa_rel_kernel<<<grid, THREADS>>>(Q, K, V, M, deAtt, attnOut);
}

// round 5
// speedup vs baseline: 1.2702x; 1.0940x over previous
#include <cuda_runtime.h>

#define SEQ 20
#define DK  64
#define BHB 2        // (b,h) problems per block
#define THREADS 256

#define QS 65        // Q,K smem row stride (q*65 mod 32 distinct -> conflict-free scalar reads)
#define VS 68        // V smem row stride (float4-aligned)
#define WS 21        // raw scores smem row stride
#define TS 28        // transposed-W row stride (float4-aligned)

__global__ __launch_bounds__(THREADS)
void sdpa_rel_kernel(const float* __restrict__ Qg,
                     const float* __restrict__ Kg,
                     const float* __restrict__ Vg,
                     const float* __restrict__ Mg,
                     float* __restrict__ deAtt,
                     float* __restrict__ attnOut)
{
    __shared__ float sQ[BHB][SEQ * QS];
    __shared__ float sK[BHB][SEQ * QS];
    __shared__ __align__(16) float sV[BHB][SEQ * VS];
    __shared__ float sS[BHB][SEQ * WS];
    __shared__ __align__(16) float sWt[BHB][SEQ * TS];   // W transposed: sWt[k*TS+q]
    __shared__ float sInv[BHB][SEQ];

    const int tid = threadIdx.x;
    const long bh0 = (long)blockIdx.x * BHB;

    // ---- Stage Q,K,V tiles into smem (float4 global loads, coalesced) ----
    for (int i = tid; i < BHB * (SEQ * DK / 4); i += THREADS) {
        int b   = i / (SEQ * DK / 4);
        int j   = i % (SEQ * DK / 4);
        int row = j / (DK / 4);
        int c4  = j % (DK / 4);
        const long base = (bh0 + b) * (long)(SEQ * DK);
        float4 q = ((const float4*)(Qg + base))[j];
        float4 k = ((const float4*)(Kg + base))[j];
        float4 v = ((const float4*)(Vg + base))[j];
        float* dq = &sQ[b][row * QS + 4 * c4];
        dq[0] = q.x; dq[1] = q.y; dq[2] = q.z; dq[3] = q.w;
        float* dk = &sK[b][row * QS + 4 * c4];
        dk[0] = k.x; dk[1] = k.y; dk[2] = k.z; dk[3] = k.w;
        *((float4*)(&sV[b][row * VS + 4 * c4])) = v;
    }
    __syncthreads();

    // ---- Phase A: S = Q K^T, 4x4 register tiles (50 active, scalar broadcast reads) ----
    if (tid < BHB * 25) {
        int b    = tid / 25;
        int tile = tid % 25;
        int q0 = (tile / 5) * 4;
        int k0 = (tile % 5) * 4;
        float acc[4][4] = {};
        #pragma unroll 8
        for (int d = 0; d < DK; d++) {
            float qv[4], kv[4];
            #pragma unroll
            for (int i = 0; i < 4; i++) qv[i] = sQ[b][(q0 + i) * QS + d];
            #pragma unroll
            for (int j = 0; j < 4; j++) kv[j] = sK[b][(k0 + j) * QS + d];
            #pragma unroll
            for (int i = 0; i < 4; i++)
                #pragma unroll
                for (int j = 0; j < 4; j++)
                    acc[i][j] = fmaf(qv[i], kv[j], acc[i][j]);
        }
        #pragma unroll
        for (int i = 0; i < 4; i++)
            #pragma unroll
            for (int j = 0; j < 4; j++)
                sS[b][(q0 + i) * WS + (k0 + j)] = acc[i][j];
    }
    __syncthreads();

    // ---- exp(scale * S) * mask (mask read coalesced from global) ----
    for (int e = tid; e < BHB * SEQ * SEQ; e += THREADS) {
        int b = e / (SEQ * SEQ);
        int j = e % (SEQ * SEQ);
        int q = j / SEQ, k = j % SEQ;
        float raw = sS[b][q * WS + k];
        sS[b][q * WS + k] = __expf(raw * 0.125f) * Mg[(bh0 + b) * (long)(SEQ * SEQ) + j];
    }
    __syncthreads();

    // ---- row sums -> reciprocal ----
    if (tid < BHB * SEQ) {
        int b = tid / SEQ, q = tid % SEQ;
        float s = 0.f;
        #pragma unroll
        for (int k = 0; k < SEQ; k++) s += sS[b][q * WS + k];
        sInv[b][q] = 1.0f / (s + 1e-8f);
    }
    __syncthreads();

    // ---- normalize -> write attn; W = attn - |q-k| stored TRANSPOSED in sWt ----
    for (int e = tid; e < BHB * SEQ * SEQ; e += THREADS) {
        int b = e / (SEQ * SEQ);
        int j = e % (SEQ * SEQ);
        int q = j / SEQ, k = j % SEQ;
        float a = sS[b][q * WS + k] * sInv[b][q];
        attnOut[(bh0 + b) * (long)(SEQ * SEQ) + j] = a;
        sWt[b][k * TS + q] = a - fabsf((float)(q - k));
    }
    __syncthreads();

    // ---- Phase C: deAtt = W @ V, 4q x 4d tiles, d0-major mapping ----
    // lanes sharing d0 are adjacent -> V LDS.128 is broadcast (1 wavefront);
    // W loaded as one float4 per k-step from the transposed buffer.
    if (tid < BHB * 80) {
        int b  = tid / 80;
        int t  = tid % 80;
        int d0 = (t / 5) * 4;        // float column start (16 groups of 4)
        int q0 = (t % 5) * 4;        // row group
        float4 acc[4];
        #pragma unroll
        for (int i = 0; i < 4; i++) acc[i] = make_float4(0.f, 0.f, 0.f, 0.f);
        #pragma unroll
        for (int k = 0; k < SEQ; k++) {
            float4 v = *((const float4*)(&sV[b][k * VS + d0]));
            float4 w = *((const float4*)(&sWt[b][k * TS + q0]));
            acc[0].x = fmaf(w.x, v.x, acc[0].x);
            acc[0].y = fmaf(w.x, v.y, acc[0].y);
            acc[0].z = fmaf(w.x, v.z, acc[0].z);
            acc[0].w = fmaf(w.x, v.w, acc[0].w);
            acc[1].x = fmaf(w.y, v.x, acc[1].x);
            acc[1].y = fmaf(w.y, v.y, acc[1].y);
            acc[1].z = fmaf(w.y, v.z, acc[1].z);
            acc[1].w = fmaf(w.y, v.w, acc[1].w);
            acc[2].x = fmaf(w.z, v.x, acc[2].x);
            acc[2].y = fmaf(w.z, v.y, acc[2].y);
            acc[2].z = fmaf(w.z, v.z, acc[2].z);
            acc[2].w = fmaf(w.z, v.w, acc[2].w);
            acc[3].x = fmaf(w.w, v.x, acc[3].x);
            acc[3].y = fmaf(w.w, v.y, acc[3].y);
            acc[3].z = fmaf(w.w, v.z, acc[3].z);
            acc[3].w = fmaf(w.w, v.w, acc[3].w);
        }
        const long base = (bh0 + b) * (long)(SEQ * DK);
        #pragma unroll
        for (int i = 0; i < 4; i++)
            *((float4*)(deAtt + base + (q0 + i) * DK + d0)) = acc[i];
    }
}

extern "C" void kernel_launch(void* const* d_in, const int* in_sizes, int n_in,
                              void* d_out, int out_size)
{
    const float* Q = (const float*)d_in[0];
    const float* K = (const float*)d_in[1];
    const float* V = (const float*)d_in[2];
    const float* M = (const float*)d_in[3];

    const int bh = in_sizes[0] / (SEQ * DK);   // 8192

    float* deAtt   = (float*)d_out;                      // [bh, SEQ, DK]
    float* attnOut = (float*)d_out + (long)in_sizes[0];  // [bh, SEQ, SEQ]

    const int grid = bh / BHB;                           // 4096
    sdpa_rel_kernel<<<grid, THREADS>>>(Q, K, V, M, deAtt, attnOut);
}